// round 15
// baseline (speedup 1.0000x reference)
#include <cuda_runtime.h>
#include <cuda_bf16.h>
#include <cuda_fp16.h>
#include <cstdint>

#define HH 160
#define WW 160
#define BB 4
#define CC 64
#define COUT 64
#define OFFC 64
#define K2 9
#define HW (HH*WW)             // 25600
#define OUT_MAIN (BB*COUT*HW)  // 6553600
#define OUT_OFF  (BB*2*K2*HW)  // 1843200
#define NBLK 800
#define EPSV 1e-5f

// ---- warp-MMA helpers (plain PTX, works on .target sm_103) ----------------
__device__ __forceinline__ uint32_t smem_u32(const void* p) {
    uint32_t a;
    asm("{ .reg .u64 t; cvta.to.shared.u64 t, %1; cvt.u32.u64 %0, t; }"
        : "=r"(a) : "l"(p));
    return a;
}
__device__ __forceinline__ void ldsm_x4(uint32_t& r0, uint32_t& r1,
                                        uint32_t& r2, uint32_t& r3, uint32_t a) {
    asm volatile("ldmatrix.sync.aligned.m8n8.x4.shared.b16 {%0,%1,%2,%3}, [%4];"
                 : "=r"(r0), "=r"(r1), "=r"(r2), "=r"(r3) : "r"(a));
}
__device__ __forceinline__ void ldsm_x4t(uint32_t& r0, uint32_t& r1,
                                         uint32_t& r2, uint32_t& r3, uint32_t a) {
    asm volatile("ldmatrix.sync.aligned.m8n8.x4.trans.shared.b16 {%0,%1,%2,%3}, [%4];"
                 : "=r"(r0), "=r"(r1), "=r"(r2), "=r"(r3) : "r"(a));
}
__device__ __forceinline__ void mma16816h(float* c, const uint32_t* a,
                                          uint32_t b0, uint32_t b1) {
    asm volatile("mma.sync.aligned.m16n8k16.row.col.f32.f16.f16.f32 "
                 "{%0,%1,%2,%3}, {%4,%5,%6,%7}, {%8,%9}, {%0,%1,%2,%3};"
                 : "+f"(c[0]), "+f"(c[1]), "+f"(c[2]), "+f"(c[3])
                 : "r"(a[0]), "r"(a[1]), "r"(a[2]), "r"(a[3]), "r"(b0), "r"(b1));
}
__device__ __forceinline__ uint32_t sw128(uint32_t off) {
    return off ^ ((off >> 3) & 0x70);
}
__device__ __forceinline__ uint32_t sw64(uint32_t off) {
    return off ^ ((off >> 3) & 0x30);
}
__device__ __forceinline__ void cp_async8(uint32_t dst, const void* src, int sz) {
    asm volatile("cp.async.ca.shared.global [%0], [%1], 8, %2;"
                 :: "r"(dst), "l"(src), "r"(sz) : "memory");
}
__device__ __forceinline__ void cp_async16(uint32_t dst, const void* src) {
    asm volatile("cp.async.ca.shared.global [%0], [%1], 16;"
                 :: "r"(dst), "l"(src) : "memory");
}
#define CP_COMMIT() asm volatile("cp.async.commit_group;" ::: "memory")
#define CP_WAIT0()  asm volatile("cp.async.wait_group 0;" ::: "memory")

// ---- global scratch -------------------------------------------------------
__device__ __half g_xf[BB*HW*CC];                // x NHWC fp16
__device__ __half g_df[BB*HW*CC];                // d NHWC fp16
__device__ __half g_wf[K2*CC*COUT];              // conv W fp16 [tap][cin][cout]
__device__ __half g_ofw[K2*OFFC*32];             // offset W fp16 [tap][cin][32pad]
__device__ float g_off[BB*2*K2*HW];              // clamped offsets NCHW
__device__ float g_bs[COUT*NBLK];                // per-block BN sums
__device__ float g_bq[COUT*NBLK];                // per-block BN sumsqs
__device__ float g_scale[COUT];
__device__ float g_shift[COUT];

// ---------------------------------------------------------------------------
// NCHW -> NHWC fp16: x (z=0), d (z=1)
// ---------------------------------------------------------------------------
__global__ void k_transpose(const float* __restrict__ x,
                            const float* __restrict__ d) {
    __shared__ float tile[32][33];
    const float* src = blockIdx.z ? d : x;
    __half* dst = blockIdx.z ? g_df : g_xf;
    int bh = blockIdx.y;
    int b = bh / HH, h = bh % HH;
    int tw = blockIdx.x % 5, tc = blockIdx.x / 5;
    int w = tw * 32 + threadIdx.x;
    #pragma unroll
    for (int i = 0; i < 4; i++) {
        int cl = threadIdx.y + i * 8;
        tile[cl][threadIdx.x] = src[((b*CC + tc*32 + cl)*HH + h)*WW + w];
    }
    __syncthreads();
    #pragma unroll
    for (int i = 0; i < 4; i++) {
        int wl = threadIdx.y + i * 8;
        int idx = ((b*HH + h)*WW + tw*32 + wl)*CC + tc*32 + threadIdx.x;
        dst[idx] = __float2half(tile[threadIdx.x][wl]);
    }
}

// ---------------------------------------------------------------------------
// conv_w -> fp16, [tap][cin][cout]
// ---------------------------------------------------------------------------
__global__ void k_wsplit(const float* __restrict__ cw) {
    int i = blockIdx.x * 256 + threadIdx.x;      // K2*CC*COUT = 36864
    if (i < K2*CC*COUT) {
        int tap = i / (CC*COUT), ci = (i / COUT) % CC, co = i % COUT;
        g_wf[i] = __float2half(cw[(co*CC + ci)*K2 + tap]);
    }
}

// ---------------------------------------------------------------------------
// offset_w -> fp16, [tap][cin][32pad] (couts 18..31 zero)
// ---------------------------------------------------------------------------
__global__ void k_owsplit(const float* __restrict__ ow) {
    int i = blockIdx.x * 256 + threadIdx.x;      // K2*OFFC*32 = 18432
    if (i < K2*OFFC*32) {
        int tap = i / (OFFC*32), ci = (i / 32) % OFFC, co = i % 32;
        float w = 0.f;
        if (co < 18) w = ow[(co*OFFC + ci)*K2 + tap];
        g_ofw[i] = __float2half(w);
    }
}

// ---------------------------------------------------------------------------
// Offset conv as single-fp16 HMMA GEMM: 256-px tiles, warp = M32 x N32.
// A via cp.async with LINEAR shifted offsets; validity from prologue bitmasks.
// ---------------------------------------------------------------------------
#define OSM_A 0
#define OSM_B 32768
#define OSM_SIZE (36864 + 1024)

__global__ __launch_bounds__(256, 4) void k_offmma(float* __restrict__ outoff) {
    extern __shared__ char smraw[];
    char* sm = (char*)(((uintptr_t)smraw + 1023) & ~(uintptr_t)1023);
    uint32_t s0 = smem_u32(sm);
    int tid = threadIdx.x, wid = tid >> 5, lid = tid & 31;
    int tile = blockIdx.x;            // 0..399
    int b = tile / 100;
    int px0 = (tile % 100) * 256;

    int l15 = lid & 15, l16 = (lid >> 4) * 8;
    int g4 = tid & 15, pxl = tid >> 4;

    // ---- prologue: boundary flags per it + linear bases ----
    uint32_t fh0 = 0, fh1 = 0, fw0 = 0, fw1 = 0;
    #pragma unroll
    for (int it = 0; it < 16; it++) {
        int pg = px0 + pxl + it * 16;
        int m = pg % WW;
        if (pg < WW)          fh0 |= 1u << it;
        if (pg >= HW - WW)    fh1 |= 1u << it;
        if (m == 0)           fw0 |= 1u << it;
        if (m == WW - 1)      fw1 |= 1u << it;
    }
    const __half* dbase = g_df + (size_t)b * HW * CC
                        + (size_t)(px0 + pxl) * CC + g4 * 4;
    uint32_t swbase = sw128((uint32_t)pxl * 128 + g4 * 8);

    float acc[2][4][4];
    #pragma unroll
    for (int mt = 0; mt < 2; mt++)
        #pragma unroll
        for (int j = 0; j < 4; j++)
            #pragma unroll
            for (int q = 0; q < 4; q++) acc[mt][j][q] = 0.f;

    for (int tap = 0; tap < 9; tap++) {
        int th = tap / 3 - 1, tw = tap % 3 - 1;
        uint32_t bad = (th < 0 ? fh0 : 0u) | (th > 0 ? fh1 : 0u)
                     | (tw < 0 ? fw0 : 0u) | (tw > 0 ? fw1 : 0u);
        int shift = (th * WW + tw) * CC;
        // ---- A: shifted linear cp.async (zero-fill invalid) ----
        #pragma unroll
        for (int it = 0; it < 16; it++) {
            bool valid = !((bad >> it) & 1u);
            const __half* src = dbase + it * (16 * CC) + (valid ? shift : 0);
            cp_async8(s0 + OSM_A + swbase + it * 2048, src, valid ? 8 : 0);
        }
        // ---- B tile: [64 cin][32 couts], 64B rows, SW64 ----
        {
            const uint4* wp = (const uint4*)g_ofw + tap * 256;
            int row = tid >> 2, q = tid & 3;
            uint32_t sw = sw64(row * 64 + q * 16);
            cp_async16(s0 + OSM_B + sw, wp + tid);
        }
        CP_COMMIT();
        CP_WAIT0();
        __syncthreads();

        // ---- MMA: warp wid -> px rows 32wid..+31, couts 0..31 ----
        #pragma unroll
        for (int ks = 0; ks < 4; ks++) {
            int k0 = ks * 16;
            uint32_t ah[2][4];
            #pragma unroll
            for (int mt = 0; mt < 2; mt++) {
                uint32_t sa = sw128((wid*32 + mt*16 + l15) * 128 + (k0 + l16) * 2);
                ldsm_x4(ah[mt][0], ah[mt][1], ah[mt][2], ah[mt][3], s0 + OSM_A + sa);
            }
            #pragma unroll
            for (int jj = 0; jj < 2; jj++) {
                uint32_t sb = sw64((k0 + l15) * 64 + (jj*16 + l16) * 2);
                uint32_t b0, b1, b2, b3;
                ldsm_x4t(b0, b1, b2, b3, s0 + OSM_B + sb);
                #pragma unroll
                for (int mt = 0; mt < 2; mt++) {
                    mma16816h(acc[mt][2*jj],   ah[mt], b0, b1);
                    mma16816h(acc[mt][2*jj+1], ah[mt], b2, b3);
                }
            }
        }
        __syncthreads();
    }

    // ---- epilogue: clamp + write offsets (NCHW [B,18,H,W]) ----
    #pragma unroll
    for (int mt = 0; mt < 2; mt++) {
        int prow = wid * 32 + mt * 16 + (lid >> 2);
        int pg0 = px0 + prow, pg1 = pg0 + 8;
        #pragma unroll
        for (int j = 0; j < 4; j++) {
            int c0 = j * 8 + (lid & 3) * 2;
            if (c0 < 18) {
                float v0 = fminf(1.f, fmaxf(-1.f, acc[mt][j][0]));
                float v2 = fminf(1.f, fmaxf(-1.f, acc[mt][j][2]));
                int i0 = (b*18 + c0)*HW + pg0;
                int i1 = (b*18 + c0)*HW + pg1;
                g_off[i0] = v0; g_off[i1] = v2;
                if (outoff) { outoff[i0] = v0; outoff[i1] = v2; }
                if (c0 + 1 < 18) {
                    float v1 = fminf(1.f, fmaxf(-1.f, acc[mt][j][1]));
                    float v3 = fminf(1.f, fmaxf(-1.f, acc[mt][j][3]));
                    g_off[i0 + HW] = v1; g_off[i1 + HW] = v3;
                    if (outoff) { outoff[i0 + HW] = v1; outoff[i1 + HW] = v3; }
                }
            }
        }
    }
}

// ---------------------------------------------------------------------------
// Main deformable conv — fp16 MMA, single-sync double-buffered pipeline:
// iteration = gather(tap,cur) + coords(tap+1,nxt) + loadB(tap,cur)
//             -> ONE sync -> MMA(tap,cur).
// Coords stored as int4 bases + half4 weights. 56.3KB smem, 4 CTAs/SM.
// ---------------------------------------------------------------------------
#define PA(buf)  ((buf) * 16384)              // A: 2 x 16KB
#define PB(buf)  (32768 + (buf) * 8192)       // B: 2 x 8KB
#define PBS(buf) (49152 + (buf) * 2048)       // bases int[512]: 2 x 2KB
#define PWT(buf) (53248 + (buf) * 1024)       // weights half[512]: 2 x 1KB
#define SM_SIZE  (55296 + 1024)

__global__ __launch_bounds__(256, 4) void k_deform(float* __restrict__ out) {
    extern __shared__ char smraw[];
    char* sm = (char*)(((uintptr_t)smraw + 1023) & ~(uintptr_t)1023);
    uint32_t s0 = smem_u32(sm);
    int tid = threadIdx.x, wid = tid >> 5, lid = tid & 31;
    int tile = blockIdx.x;            // 0..799
    int b = tile / 200;
    int px0 = (tile % 200) * 128;

    int mw = wid & 3, nw = wid >> 2;
    int l15 = lid & 15, l16 = (lid >> 4) * 8;
    int g4 = tid & 15;
    uint32_t swg = sw128(((uint32_t)(tid >> 4)) * 128 + g4 * 8);

    float acc[2][4][4];
    #pragma unroll
    for (int mt = 0; mt < 2; mt++)
        #pragma unroll
        for (int j = 0; j < 4; j++)
            #pragma unroll
            for (int q = 0; q < 4; q++) acc[mt][j][q] = 0.f;

    // ---- coords for one tap -> buffer buf ----
    auto coords = [&](int tap, int buf) {
        int px = tid >> 1;
        int pg = px0 + px;
        int h = pg / WW, w = pg % WW;
        float dy = g_off[(b*18 + 2*tap    )*HW + pg];
        float dx = g_off[(b*18 + 2*tap + 1)*HW + pg];
        float py = (float)h - 1.f + (float)(tap / 3) + dy;
        float pxx = (float)w - 1.f + (float)(tap % 3) + dx;
        float y0f = floorf(py), x0f = floorf(pxx);
        float fy = py - y0f, fx = pxx - x0f;
        int y0 = (int)y0f, x0 = (int)x0f;
        int jj = tid & 1;                 // corner pair: jj=0 -> cn0,1 ; jj=1 -> cn2,3
        int cb[2]; __half chw[2];
        #pragma unroll
        for (int j = 0; j < 2; j++) {
            int yy = y0 + jj, xx = x0 + j;
            float wt = (jj ? fy : 1.f - fy) * (j ? fx : 1.f - fx);
            bool valid = (yy >= 0) && (yy < HH) && (xx >= 0) && (xx < WW);
            int yc = min(max(yy, 0), HH - 1), xc = min(max(xx, 0), WW - 1);
            cb[j] = ((b*HH + yc)*WW + xc) * CC;
            chw[j] = __float2half(valid ? wt : 0.f);
        }
        *(int2*)(sm + PBS(buf) + px*16 + jj*8) = make_int2(cb[0], cb[1]);
        __half2 hv = __halves2half2(chw[0], chw[1]);
        *(uint32_t*)(sm + PWT(buf) + px*8 + jj*4) = *(uint32_t*)&hv;
    };

    // ---- gather one tap from buffer buf -> A[buf] ----
    auto gather = [&](int buf) {
        const uint2* xq = (const uint2*)g_xf;
        #pragma unroll 4
        for (int it = 0; it < 8; it++) {
            int px = (tid >> 4) + it * 16;
            int4 cb = *(const int4*)(sm + PBS(buf) + px*16);
            uint2 wq = *(const uint2*)(sm + PWT(buf) + px*8);
            __half2 wa = *(__half2*)&wq.x, wb = *(__half2*)&wq.y;
            float w0 = __low2float(wa), w1 = __high2float(wa);
            float w2 = __low2float(wb), w3 = __high2float(wb);
            uint2 r0 = xq[(cb.x >> 2) + g4];
            uint2 r1 = xq[(cb.y >> 2) + g4];
            uint2 r2 = xq[(cb.z >> 2) + g4];
            uint2 r3 = xq[(cb.w >> 2) + g4];
            float2 a0x = __half22float2(*(__half2*)&r0.x), a0y = __half22float2(*(__half2*)&r0.y);
            float2 a1x = __half22float2(*(__half2*)&r1.x), a1y = __half22float2(*(__half2*)&r1.y);
            float2 a2x = __half22float2(*(__half2*)&r2.x), a2y = __half22float2(*(__half2*)&r2.y);
            float2 a3x = __half22float2(*(__half2*)&r3.x), a3y = __half22float2(*(__half2*)&r3.y);
            float4 v;
            v.x = w0*a0x.x + w1*a1x.x + w2*a2x.x + w3*a3x.x;
            v.y = w0*a0x.y + w1*a1x.y + w2*a2x.y + w3*a3x.y;
            v.z = w0*a0y.x + w1*a1y.x + w2*a2y.x + w3*a3y.x;
            v.w = w0*a0y.y + w1*a1y.y + w2*a2y.y + w3*a3y.y;
            __half2 p01 = __floats2half2_rn(v.x, v.y);
            __half2 p23 = __floats2half2_rn(v.z, v.w);
            uint2 hv;
            hv.x = *(uint32_t*)&p01; hv.y = *(uint32_t*)&p23;
            *(uint2*)(sm + PA(buf) + swg + it * 2048) = hv;
        }
    };

    auto loadB = [&](int tap, int buf) {
        const uint4* wh = (const uint4*)g_wf + tap * 512;
        #pragma unroll
        for (int i = tid; i < 512; i += 256) {
            int row = i >> 3, gq = i & 7;
            uint32_t sw = sw128(row * 128 + gq * 16);
            *(uint4*)(sm + PB(buf) + sw) = wh[i];
        }
    };

    // ---- prologue ----
    coords(0, 0);
    __syncthreads();

    for (int tap = 0; tap < 9; tap++) {
        int cur = tap & 1, nxt = cur ^ 1;
        gather(cur);
        if (tap < 8) coords(tap + 1, nxt);
        loadB(tap, cur);
        __syncthreads();

        #pragma unroll
        for (int ks = 0; ks < 4; ks++) {
            int k0 = ks * 16;
            uint32_t ah[2][4];
            #pragma unroll
            for (int mt = 0; mt < 2; mt++) {
                uint32_t sa = sw128((mw*32 + mt*16 + l15) * 128 + (k0 + l16) * 2);
                ldsm_x4(ah[mt][0], ah[mt][1], ah[mt][2], ah[mt][3],
                        s0 + PA(cur) + sa);
            }
            #pragma unroll
            for (int jj = 0; jj < 2; jj++) {
                uint32_t sb = sw128((k0 + l15) * 128 + (nw*32 + jj*16 + l16) * 2);
                uint32_t b0, b1, b2, b3;
                ldsm_x4t(b0, b1, b2, b3, s0 + PB(cur) + sb);
                #pragma unroll
                for (int mt = 0; mt < 2; mt++) {
                    mma16816h(acc[mt][2*jj],   ah[mt], b0, b1);
                    mma16816h(acc[mt][2*jj+1], ah[mt], b2, b3);
                }
            }
        }
    }
    __syncthreads();   // MMA(8) done in all warps before smem reuse below

    // ---- epilogue: fragments -> NCHW ----
    {
        float* op = out + (size_t)b * COUT * HW;
        #pragma unroll
        for (int mt = 0; mt < 2; mt++) {
            int prow = px0 + mw*32 + mt*16 + (lid >> 2);
            #pragma unroll
            for (int j = 0; j < 4; j++) {
                int c0 = nw*32 + j*8 + (lid & 3) * 2;
                op[(c0    ) * HW + prow    ] = acc[mt][j][0];
                op[(c0 + 1) * HW + prow    ] = acc[mt][j][1];
                op[(c0    ) * HW + prow + 8] = acc[mt][j][2];
                op[(c0 + 1) * HW + prow + 8] = acc[mt][j][3];
            }
        }
    }

    // ---- fused BN partial stats (deterministic) ----
    {
        float ps[8], pq[8];
        #pragma unroll
        for (int j = 0; j < 4; j++) {
            float s0v = 0.f, s1v = 0.f, q0v = 0.f, q1v = 0.f;
            #pragma unroll
            for (int mt = 0; mt < 2; mt++) {
                float a = acc[mt][j][0], bb = acc[mt][j][1];
                float cvv = acc[mt][j][2], dv = acc[mt][j][3];
                s0v += a + cvv;          s1v += bb + dv;
                q0v += a*a + cvv*cvv;    q1v += bb*bb + dv*dv;
            }
            ps[2*j] = s0v; ps[2*j+1] = s1v;
            pq[2*j] = q0v; pq[2*j+1] = q1v;
        }
        #pragma unroll
        for (int v = 0; v < 8; v++) {
            #pragma unroll
            for (int off = 16; off >= 4; off >>= 1) {
                ps[v] += __shfl_down_sync(0xffffffffu, ps[v], off);
                pq[v] += __shfl_down_sync(0xffffffffu, pq[v], off);
            }
        }
        float* sred = (float*)sm;   // smem free after last sync
        if (lid < 4) {
            float* row = sred + wid*64 + lid*16;
            #pragma unroll
            for (int j = 0; j < 4; j++) {
                row[j*4 + 0] = ps[2*j];
                row[j*4 + 1] = ps[2*j + 1];
                row[j*4 + 2] = pq[2*j];
                row[j*4 + 3] = pq[2*j + 1];
            }
        }
        __syncthreads();
        if (tid < 128) {
            int c = tid >> 1, isq = tid & 1;
            int nw2 = c >> 5, local = c & 31;
            int j = local >> 3, l = (local & 7) >> 1, pair = local & 1;
            int idx = l*16 + j*4 + pair + (isq ? 2 : 0);
            float v = sred[(nw2*4 + 0)*64 + idx] + sred[(nw2*4 + 1)*64 + idx]
                    + sred[(nw2*4 + 2)*64 + idx] + sred[(nw2*4 + 3)*64 + idx];
            if (isq) g_bq[c*NBLK + blockIdx.x] = v;
            else     g_bs[c*NBLK + blockIdx.x] = v;
        }
    }
}

// ---------------------------------------------------------------------------
// Finalize BN: one block per channel, reduce 800 partials (deterministic)
// ---------------------------------------------------------------------------
__global__ void k_finalize(const float* __restrict__ gamma,
                           const float* __restrict__ beta) {
    int c = blockIdx.x;
    __shared__ float rs[256], rq[256];
    float s = 0.f, q = 0.f;
    for (int i = threadIdx.x; i < NBLK; i += 256) {
        s += g_bs[c*NBLK + i];
        q += g_bq[c*NBLK + i];
    }
    rs[threadIdx.x] = s; rq[threadIdx.x] = q;
    __syncthreads();
    for (int st = 128; st > 0; st >>= 1) {
        if (threadIdx.x < st) {
            rs[threadIdx.x] += rs[threadIdx.x + st];
            rq[threadIdx.x] += rq[threadIdx.x + st];
        }
        __syncthreads();
    }
    if (threadIdx.x == 0) {
        float inv_n = 1.f / (float)(BB * HW);
        float mean = rs[0] * inv_n;
        float var  = rq[0] * inv_n - mean * mean;
        float sc = gamma[c] * rsqrtf(var + EPSV);
        g_scale[c] = sc;
        g_shift[c] = beta[c] - mean * sc;
    }
}

__global__ void k_bnrelu(float* __restrict__ out) {
    int idx = blockIdx.x * 256 + threadIdx.x;
    int c = (idx / (HW / 4)) & 63;
    float sc = g_scale[c], sh = g_shift[c];
    float4 v = ((float4*)out)[idx];
    v.x = fmaxf(0.f, v.x * sc + sh);
    v.y = fmaxf(0.f, v.y * sc + sh);
    v.z = fmaxf(0.f, v.z * sc + sh);
    v.w = fmaxf(0.f, v.w * sc + sh);
    ((float4*)out)[idx] = v;
}

// ---------------------------------------------------------------------------
extern "C" void kernel_launch(void* const* d_in, const int* in_sizes, int n_in,
                              void* d_out, int out_size) {
    const float* x     = (const float*)d_in[0];
    const float* d     = (const float*)d_in[1];
    const float* ow    = (const float*)d_in[2];
    const float* cw    = (const float*)d_in[3];
    const float* gamma = (const float*)d_in[4];
    const float* beta  = (const float*)d_in[5];
    float* out = (float*)d_out;
    float* outoff = (out_size >= OUT_MAIN + OUT_OFF) ? (out + OUT_MAIN) : nullptr;

    cudaFuncSetAttribute(k_deform, cudaFuncAttributeMaxDynamicSharedMemorySize,
                         SM_SIZE);
    cudaFuncSetAttribute(k_offmma, cudaFuncAttributeMaxDynamicSharedMemorySize,
                         OSM_SIZE);

    k_transpose<<<dim3(10, BB * HH, 2), dim3(32, 8)>>>(x, d);
    k_wsplit<<<(K2 * CC * COUT + 255) / 256, 256>>>(cw);
    k_owsplit<<<(K2 * OFFC * 32 + 255) / 256, 256>>>(ow);
    k_offmma<<<400, 256, OSM_SIZE>>>(outoff);
    k_deform<<<NBLK, 256, SM_SIZE>>>(out);
    k_finalize<<<COUT, 256>>>(gamma, beta);
    k_bnrelu<<<OUT_MAIN / 4 / 256, 256>>>(out);
}

// round 17
// speedup vs baseline: 1.0533x; 1.0533x over previous
#include <cuda_runtime.h>
#include <cuda_bf16.h>
#include <cuda_fp16.h>
#include <cstdint>

#define HH 160
#define WW 160
#define BB 4
#define CC 64
#define COUT 64
#define OFFC 64
#define K2 9
#define HW (HH*WW)             // 25600
#define OUT_MAIN (BB*COUT*HW)  // 6553600
#define OUT_OFF  (BB*2*K2*HW)  // 1843200
#define NBLK 800
#define EPSV 1e-5f

// ---- warp-MMA helpers (plain PTX, works on .target sm_103) ----------------
__device__ __forceinline__ uint32_t smem_u32(const void* p) {
    uint32_t a;
    asm("{ .reg .u64 t; cvta.to.shared.u64 t, %1; cvt.u32.u64 %0, t; }"
        : "=r"(a) : "l"(p));
    return a;
}
__device__ __forceinline__ void ldsm_x4(uint32_t& r0, uint32_t& r1,
                                        uint32_t& r2, uint32_t& r3, uint32_t a) {
    asm volatile("ldmatrix.sync.aligned.m8n8.x4.shared.b16 {%0,%1,%2,%3}, [%4];"
                 : "=r"(r0), "=r"(r1), "=r"(r2), "=r"(r3) : "r"(a));
}
__device__ __forceinline__ void ldsm_x4t(uint32_t& r0, uint32_t& r1,
                                         uint32_t& r2, uint32_t& r3, uint32_t a) {
    asm volatile("ldmatrix.sync.aligned.m8n8.x4.trans.shared.b16 {%0,%1,%2,%3}, [%4];"
                 : "=r"(r0), "=r"(r1), "=r"(r2), "=r"(r3) : "r"(a));
}
__device__ __forceinline__ void mma16816h(float* c, const uint32_t* a,
                                          uint32_t b0, uint32_t b1) {
    asm volatile("mma.sync.aligned.m16n8k16.row.col.f32.f16.f16.f32 "
                 "{%0,%1,%2,%3}, {%4,%5,%6,%7}, {%8,%9}, {%0,%1,%2,%3};"
                 : "+f"(c[0]), "+f"(c[1]), "+f"(c[2]), "+f"(c[3])
                 : "r"(a[0]), "r"(a[1]), "r"(a[2]), "r"(a[3]), "r"(b0), "r"(b1));
}
__device__ __forceinline__ uint32_t sw128(uint32_t off) {
    return off ^ ((off >> 3) & 0x70);
}
__device__ __forceinline__ uint32_t sw64(uint32_t off) {
    return off ^ ((off >> 3) & 0x30);
}
__device__ __forceinline__ void cp_async8(uint32_t dst, const void* src, int sz) {
    asm volatile("cp.async.ca.shared.global [%0], [%1], 8, %2;"
                 :: "r"(dst), "l"(src), "r"(sz) : "memory");
}
__device__ __forceinline__ void cp_async16(uint32_t dst, const void* src) {
    asm volatile("cp.async.ca.shared.global [%0], [%1], 16;"
                 :: "r"(dst), "l"(src) : "memory");
}
#define CP_COMMIT() asm volatile("cp.async.commit_group;" ::: "memory")
#define CP_WAIT0()  asm volatile("cp.async.wait_group 0;" ::: "memory")

// ---- global scratch -------------------------------------------------------
__device__ __half g_xf[BB*HW*CC];                // x NHWC fp16
__device__ __half g_df[BB*HW*CC];                // d NHWC fp16
__device__ __half g_wf[K2*CC*COUT];              // conv W fp16 [tap][cin][cout]
__device__ __half g_ofw[K2*OFFC*32];             // offset W fp16 [tap][cin][32pad]
__device__ float g_off[BB*2*K2*HW];              // clamped offsets NCHW
__device__ float g_bs[COUT*NBLK];                // per-block BN sums
__device__ float g_bq[COUT*NBLK];                // per-block BN sumsqs
__device__ float g_scale[COUT];
__device__ float g_shift[COUT];

// ---------------------------------------------------------------------------
// NCHW -> NHWC fp16: x (z=0), d (z=1)
// ---------------------------------------------------------------------------
__global__ void k_transpose(const float* __restrict__ x,
                            const float* __restrict__ d) {
    __shared__ float tile[32][33];
    const float* src = blockIdx.z ? d : x;
    __half* dst = blockIdx.z ? g_df : g_xf;
    int bh = blockIdx.y;
    int b = bh / HH, h = bh % HH;
    int tw = blockIdx.x % 5, tc = blockIdx.x / 5;
    int w = tw * 32 + threadIdx.x;
    #pragma unroll
    for (int i = 0; i < 4; i++) {
        int cl = threadIdx.y + i * 8;
        tile[cl][threadIdx.x] = src[((b*CC + tc*32 + cl)*HH + h)*WW + w];
    }
    __syncthreads();
    #pragma unroll
    for (int i = 0; i < 4; i++) {
        int wl = threadIdx.y + i * 8;
        int idx = ((b*HH + h)*WW + tw*32 + wl)*CC + tc*32 + threadIdx.x;
        dst[idx] = __float2half(tile[threadIdx.x][wl]);
    }
}

// ---------------------------------------------------------------------------
// conv_w -> fp16, [tap][cin][cout]
// ---------------------------------------------------------------------------
__global__ void k_wsplit(const float* __restrict__ cw) {
    int i = blockIdx.x * 256 + threadIdx.x;      // K2*CC*COUT = 36864
    if (i < K2*CC*COUT) {
        int tap = i / (CC*COUT), ci = (i / COUT) % CC, co = i % COUT;
        g_wf[i] = __float2half(cw[(co*CC + ci)*K2 + tap]);
    }
}

// ---------------------------------------------------------------------------
// offset_w -> fp16, [tap][cin][32pad] (couts 18..31 zero)
// ---------------------------------------------------------------------------
__global__ void k_owsplit(const float* __restrict__ ow) {
    int i = blockIdx.x * 256 + threadIdx.x;      // K2*OFFC*32 = 18432
    if (i < K2*OFFC*32) {
        int tap = i / (OFFC*32), ci = (i / 32) % OFFC, co = i % 32;
        float w = 0.f;
        if (co < 18) w = ow[(co*OFFC + ci)*K2 + tap];
        g_ofw[i] = __float2half(w);
    }
}

// ---------------------------------------------------------------------------
// Offset conv as single-fp16 HMMA GEMM (unchanged from R15 — linear cp.async)
// ---------------------------------------------------------------------------
#define OSM_A 0
#define OSM_B 32768
#define OSM_SIZE (36864 + 1024)

__global__ __launch_bounds__(256, 4) void k_offmma(float* __restrict__ outoff) {
    extern __shared__ char smraw[];
    char* sm = (char*)(((uintptr_t)smraw + 1023) & ~(uintptr_t)1023);
    uint32_t s0 = smem_u32(sm);
    int tid = threadIdx.x, wid = tid >> 5, lid = tid & 31;
    int tile = blockIdx.x;            // 0..399
    int b = tile / 100;
    int px0 = (tile % 100) * 256;

    int l15 = lid & 15, l16 = (lid >> 4) * 8;
    int g4 = tid & 15, pxl = tid >> 4;

    uint32_t fh0 = 0, fh1 = 0, fw0 = 0, fw1 = 0;
    #pragma unroll
    for (int it = 0; it < 16; it++) {
        int pg = px0 + pxl + it * 16;
        int m = pg % WW;
        if (pg < WW)          fh0 |= 1u << it;
        if (pg >= HW - WW)    fh1 |= 1u << it;
        if (m == 0)           fw0 |= 1u << it;
        if (m == WW - 1)      fw1 |= 1u << it;
    }
    const __half* dbase = g_df + (size_t)b * HW * CC
                        + (size_t)(px0 + pxl) * CC + g4 * 4;
    uint32_t swbase = sw128((uint32_t)pxl * 128 + g4 * 8);

    float acc[2][4][4];
    #pragma unroll
    for (int mt = 0; mt < 2; mt++)
        #pragma unroll
        for (int j = 0; j < 4; j++)
            #pragma unroll
            for (int q = 0; q < 4; q++) acc[mt][j][q] = 0.f;

    for (int tap = 0; tap < 9; tap++) {
        int th = tap / 3 - 1, tw = tap % 3 - 1;
        uint32_t bad = (th < 0 ? fh0 : 0u) | (th > 0 ? fh1 : 0u)
                     | (tw < 0 ? fw0 : 0u) | (tw > 0 ? fw1 : 0u);
        int shift = (th * WW + tw) * CC;
        #pragma unroll
        for (int it = 0; it < 16; it++) {
            bool valid = !((bad >> it) & 1u);
            const __half* src = dbase + it * (16 * CC) + (valid ? shift : 0);
            cp_async8(s0 + OSM_A + swbase + it * 2048, src, valid ? 8 : 0);
        }
        {
            const uint4* wp = (const uint4*)g_ofw + tap * 256;
            int row = tid >> 2, q = tid & 3;
            uint32_t sw = sw64(row * 64 + q * 16);
            cp_async16(s0 + OSM_B + sw, wp + tid);
        }
        CP_COMMIT();
        CP_WAIT0();
        __syncthreads();

        #pragma unroll
        for (int ks = 0; ks < 4; ks++) {
            int k0 = ks * 16;
            uint32_t ah[2][4];
            #pragma unroll
            for (int mt = 0; mt < 2; mt++) {
                uint32_t sa = sw128((wid*32 + mt*16 + l15) * 128 + (k0 + l16) * 2);
                ldsm_x4(ah[mt][0], ah[mt][1], ah[mt][2], ah[mt][3], s0 + OSM_A + sa);
            }
            #pragma unroll
            for (int jj = 0; jj < 2; jj++) {
                uint32_t sb = sw64((k0 + l15) * 64 + (jj*16 + l16) * 2);
                uint32_t b0, b1, b2, b3;
                ldsm_x4t(b0, b1, b2, b3, s0 + OSM_B + sb);
                #pragma unroll
                for (int mt = 0; mt < 2; mt++) {
                    mma16816h(acc[mt][2*jj],   ah[mt], b0, b1);
                    mma16816h(acc[mt][2*jj+1], ah[mt], b2, b3);
                }
            }
        }
        __syncthreads();
    }

    #pragma unroll
    for (int mt = 0; mt < 2; mt++) {
        int prow = wid * 32 + mt * 16 + (lid >> 2);
        int pg0 = px0 + prow, pg1 = pg0 + 8;
        #pragma unroll
        for (int j = 0; j < 4; j++) {
            int c0 = j * 8 + (lid & 3) * 2;
            if (c0 < 18) {
                float v0 = fminf(1.f, fmaxf(-1.f, acc[mt][j][0]));
                float v2 = fminf(1.f, fmaxf(-1.f, acc[mt][j][2]));
                int i0 = (b*18 + c0)*HW + pg0;
                int i1 = (b*18 + c0)*HW + pg1;
                g_off[i0] = v0; g_off[i1] = v2;
                if (outoff) { outoff[i0] = v0; outoff[i1] = v2; }
                if (c0 + 1 < 18) {
                    float v1 = fminf(1.f, fmaxf(-1.f, acc[mt][j][1]));
                    float v3 = fminf(1.f, fmaxf(-1.f, acc[mt][j][3]));
                    g_off[i0 + HW] = v1; g_off[i1 + HW] = v3;
                    if (outoff) { outoff[i0 + HW] = v1; outoff[i1 + HW] = v3; }
                }
            }
        }
    }
}

// ---------------------------------------------------------------------------
// Main deformable conv — fp16 MMA, 2-sync loop:
//   [gather(LDG.128) + B cp.async] sync [coords(t+1) ; MMA(t)] sync
// Single-buffered A/B/coords; fp32 coord weights. 28.7KB smem, 4 CTAs/SM.
// ---------------------------------------------------------------------------
#define PA   0                 // A tile: 16KB
#define PB   16384             // B tile: 8KB
#define PBS  24576             // bases int4[128]: 2KB
#define PWT  26624             // weights float4[128]: 2KB
#define SM_SIZE (28672 + 1024)

__global__ __launch_bounds__(256, 4) void k_deform(float* __restrict__ out) {
    extern __shared__ char smraw[];
    char* sm = (char*)(((uintptr_t)smraw + 1023) & ~(uintptr_t)1023);
    uint32_t s0 = smem_u32(sm);
    int tid = threadIdx.x, wid = tid >> 5, lid = tid & 31;
    int tile = blockIdx.x;            // 0..799
    int b = tile / 200;
    int px0 = (tile % 200) * 128;

    int mw = wid & 3, nw = wid >> 2;
    int l15 = lid & 15, l16 = (lid >> 4) * 8;
    int g8 = tid & 7;
    uint32_t swg = sw128(((uint32_t)(tid >> 3)) * 128 + g8 * 16);

    float acc[2][4][4];
    #pragma unroll
    for (int mt = 0; mt < 2; mt++)
        #pragma unroll
        for (int j = 0; j < 4; j++)
            #pragma unroll
            for (int q = 0; q < 4; q++) acc[mt][j][q] = 0.f;

    // ---- coords for one tap -> PBS/PWT (fp32 weights) ----
    auto coords = [&](int tap) {
        int px = tid >> 1;
        int pg = px0 + px;
        int h = pg / WW, w = pg % WW;
        float dy = g_off[(b*18 + 2*tap    )*HW + pg];
        float dx = g_off[(b*18 + 2*tap + 1)*HW + pg];
        float py = (float)h - 1.f + (float)(tap / 3) + dy;
        float pxx = (float)w - 1.f + (float)(tap % 3) + dx;
        float y0f = floorf(py), x0f = floorf(pxx);
        float fy = py - y0f, fx = pxx - x0f;
        int y0 = (int)y0f, x0 = (int)x0f;
        int jj = tid & 1;                 // jj=0 -> corners 0,1 ; jj=1 -> 2,3
        int cb[2]; float cw[2];
        #pragma unroll
        for (int j = 0; j < 2; j++) {
            int yy = y0 + jj, xx = x0 + j;
            float wt = (jj ? fy : 1.f - fy) * (j ? fx : 1.f - fx);
            bool valid = (yy >= 0) && (yy < HH) && (xx >= 0) && (xx < WW);
            int yc = min(max(yy, 0), HH - 1), xc = min(max(xx, 0), WW - 1);
            cb[j] = ((b*HH + yc)*WW + xc) * CC;
            cw[j] = valid ? wt : 0.f;
        }
        *(int2*)(sm + PBS + px*16 + jj*8)   = make_int2(cb[0], cb[1]);
        *(float2*)(sm + PWT + px*16 + jj*8) = make_float2(cw[0], cw[1]);
    };

    // ---- gather: 8 channels/thread via LDG.128 ----
    auto gather = [&]() {
        const uint4* xq = (const uint4*)g_xf;
        #pragma unroll
        for (int it = 0; it < 4; it++) {
            int px = (tid >> 3) + it * 32;
            int4 cb = *(const int4*)(sm + PBS + px*16);
            float4 wv = *(const float4*)(sm + PWT + px*16);
            uint4 r0 = xq[(cb.x >> 3) + g8];
            uint4 r1 = xq[(cb.y >> 3) + g8];
            uint4 r2 = xq[(cb.z >> 3) + g8];
            uint4 r3 = xq[(cb.w >> 3) + g8];
            uint4 hv;
            uint32_t* rp0 = (uint32_t*)&r0;
            uint32_t* rp1 = (uint32_t*)&r1;
            uint32_t* rp2 = (uint32_t*)&r2;
            uint32_t* rp3 = (uint32_t*)&r3;
            uint32_t* hp = (uint32_t*)&hv;
            #pragma unroll
            for (int j = 0; j < 4; j++) {
                float2 a0 = __half22float2(*(__half2*)&rp0[j]);
                float2 a1 = __half22float2(*(__half2*)&rp1[j]);
                float2 a2 = __half22float2(*(__half2*)&rp2[j]);
                float2 a3 = __half22float2(*(__half2*)&rp3[j]);
                float vx = wv.x*a0.x + wv.y*a1.x + wv.z*a2.x + wv.w*a3.x;
                float vy = wv.x*a0.y + wv.y*a1.y + wv.z*a2.y + wv.w*a3.y;
                __half2 p = __floats2half2_rn(vx, vy);
                hp[j] = *(uint32_t*)&p;
            }
            *(uint4*)(sm + PA + swg + it * 4096) = hv;
        }
    };

    // ---- prologue ----
    coords(0);
    __syncthreads();

    for (int tap = 0; tap < 9; tap++) {
        gather();
        {   // B tile via cp.async (overlaps with gather LDGs)
            const uint4* wh = (const uint4*)g_wf + tap * 512;
            #pragma unroll
            for (int i = tid; i < 512; i += 256) {
                int row = i >> 3, gq = i & 7;
                uint32_t sw = sw128(row * 128 + gq * 16);
                cp_async16(s0 + PB + sw, wh + i);
            }
        }
        CP_COMMIT();
        CP_WAIT0();
        __syncthreads();

        if (tap < 8) coords(tap + 1);   // LDGs issue early, hide under MMA

        #pragma unroll
        for (int ks = 0; ks < 4; ks++) {
            int k0 = ks * 16;
            uint32_t ah[2][4];
            #pragma unroll
            for (int mt = 0; mt < 2; mt++) {
                uint32_t sa = sw128((mw*32 + mt*16 + l15) * 128 + (k0 + l16) * 2);
                ldsm_x4(ah[mt][0], ah[mt][1], ah[mt][2], ah[mt][3], s0 + PA + sa);
            }
            #pragma unroll
            for (int jj = 0; jj < 2; jj++) {
                uint32_t sb = sw128((k0 + l15) * 128 + (nw*32 + jj*16 + l16) * 2);
                uint32_t b0, b1, b2, b3;
                ldsm_x4t(b0, b1, b2, b3, s0 + PB + sb);
                #pragma unroll
                for (int mt = 0; mt < 2; mt++) {
                    mma16816h(acc[mt][2*jj],   ah[mt], b0, b1);
                    mma16816h(acc[mt][2*jj+1], ah[mt], b2, b3);
                }
            }
        }
        __syncthreads();
    }

    // ---- epilogue: fragments -> NCHW ----
    {
        float* op = out + (size_t)b * COUT * HW;
        #pragma unroll
        for (int mt = 0; mt < 2; mt++) {
            int prow = px0 + mw*32 + mt*16 + (lid >> 2);
            #pragma unroll
            for (int j = 0; j < 4; j++) {
                int c0 = nw*32 + j*8 + (lid & 3) * 2;
                op[(c0    ) * HW + prow    ] = acc[mt][j][0];
                op[(c0 + 1) * HW + prow    ] = acc[mt][j][1];
                op[(c0    ) * HW + prow + 8] = acc[mt][j][2];
                op[(c0 + 1) * HW + prow + 8] = acc[mt][j][3];
            }
        }
    }

    // ---- fused BN partial stats (deterministic) ----
    {
        float ps[8], pq[8];
        #pragma unroll
        for (int j = 0; j < 4; j++) {
            float s0v = 0.f, s1v = 0.f, q0v = 0.f, q1v = 0.f;
            #pragma unroll
            for (int mt = 0; mt < 2; mt++) {
                float a = acc[mt][j][0], bb = acc[mt][j][1];
                float cvv = acc[mt][j][2], dv = acc[mt][j][3];
                s0v += a + cvv;          s1v += bb + dv;
                q0v += a*a + cvv*cvv;    q1v += bb*bb + dv*dv;
            }
            ps[2*j] = s0v; ps[2*j+1] = s1v;
            pq[2*j] = q0v; pq[2*j+1] = q1v;
        }
        #pragma unroll
        for (int v = 0; v < 8; v++) {
            #pragma unroll
            for (int off = 16; off >= 4; off >>= 1) {
                ps[v] += __shfl_down_sync(0xffffffffu, ps[v], off);
                pq[v] += __shfl_down_sync(0xffffffffu, pq[v], off);
            }
        }
        float* sred = (float*)sm;   // smem free after last sync
        if (lid < 4) {
            float* row = sred + wid*64 + lid*16;
            #pragma unroll
            for (int j = 0; j < 4; j++) {
                row[j*4 + 0] = ps[2*j];
                row[j*4 + 1] = ps[2*j + 1];
                row[j*4 + 2] = pq[2*j];
                row[j*4 + 3] = pq[2*j + 1];
            }
        }
        __syncthreads();
        if (tid < 128) {
            int c = tid >> 1, isq = tid & 1;
            int nw2 = c >> 5, local = c & 31;
            int j = local >> 3, l = (local & 7) >> 1, pair = local & 1;
            int idx = l*16 + j*4 + pair + (isq ? 2 : 0);
            float v = sred[(nw2*4 + 0)*64 + idx] + sred[(nw2*4 + 1)*64 + idx]
                    + sred[(nw2*4 + 2)*64 + idx] + sred[(nw2*4 + 3)*64 + idx];
            if (isq) g_bq[c*NBLK + blockIdx.x] = v;
            else     g_bs[c*NBLK + blockIdx.x] = v;
        }
    }
}

// ---------------------------------------------------------------------------
// Finalize BN: one block per channel, reduce 800 partials (deterministic)
// ---------------------------------------------------------------------------
__global__ void k_finalize(const float* __restrict__ gamma,
                           const float* __restrict__ beta) {
    int c = blockIdx.x;
    __shared__ float rs[256], rq[256];
    float s = 0.f, q = 0.f;
    for (int i = threadIdx.x; i < NBLK; i += 256) {
        s += g_bs[c*NBLK + i];
        q += g_bq[c*NBLK + i];
    }
    rs[threadIdx.x] = s; rq[threadIdx.x] = q;
    __syncthreads();
    for (int st = 128; st > 0; st >>= 1) {
        if (threadIdx.x < st) {
            rs[threadIdx.x] += rs[threadIdx.x + st];
            rq[threadIdx.x] += rq[threadIdx.x + st];
        }
        __syncthreads();
    }
    if (threadIdx.x == 0) {
        float inv_n = 1.f / (float)(BB * HW);
        float mean = rs[0] * inv_n;
        float var  = rq[0] * inv_n - mean * mean;
        float sc = gamma[c] * rsqrtf(var + EPSV);
        g_scale[c] = sc;
        g_shift[c] = beta[c] - mean * sc;
    }
}

__global__ void k_bnrelu(float* __restrict__ out) {
    int idx = blockIdx.x * 256 + threadIdx.x;
    int c = (idx / (HW / 4)) & 63;
    float sc = g_scale[c], sh = g_shift[c];
    float4 v = ((float4*)out)[idx];
    v.x = fmaxf(0.f, v.x * sc + sh);
    v.y = fmaxf(0.f, v.y * sc + sh);
    v.z = fmaxf(0.f, v.z * sc + sh);
    v.w = fmaxf(0.f, v.w * sc + sh);
    ((float4*)out)[idx] = v;
}

// ---------------------------------------------------------------------------
extern "C" void kernel_launch(void* const* d_in, const int* in_sizes, int n_in,
                              void* d_out, int out_size) {
    const float* x     = (const float*)d_in[0];
    const float* d     = (const float*)d_in[1];
    const float* ow    = (const float*)d_in[2];
    const float* cw    = (const float*)d_in[3];
    const float* gamma = (const float*)d_in[4];
    const float* beta  = (const float*)d_in[5];
    float* out = (float*)d_out;
    float* outoff = (out_size >= OUT_MAIN + OUT_OFF) ? (out + OUT_MAIN) : nullptr;

    cudaFuncSetAttribute(k_deform, cudaFuncAttributeMaxDynamicSharedMemorySize,
                         SM_SIZE);
    cudaFuncSetAttribute(k_offmma, cudaFuncAttributeMaxDynamicSharedMemorySize,
                         OSM_SIZE);

    k_transpose<<<dim3(10, BB * HH, 2), dim3(32, 8)>>>(x, d);
    k_wsplit<<<(K2 * CC * COUT + 255) / 256, 256>>>(cw);
    k_owsplit<<<(K2 * OFFC * 32 + 255) / 256, 256>>>(ow);
    k_offmma<<<400, 256, OSM_SIZE>>>(outoff);
    k_deform<<<NBLK, 256, SM_SIZE>>>(out);
    k_finalize<<<COUT, 256>>>(gamma, beta);
    k_bnrelu<<<OUT_MAIN / 4 / 256, 256>>>(out);
}